// round 5
// baseline (speedup 1.0000x reference)
#include <cuda_runtime.h>

// XY model log-density: out[s] = sum_i cos(x[up(i)] - x[i]) + cos(x[right(i)] - x[i])
// 64x64 lattice (4096 sites), 16384 samples, BETA = 1.
//
// R5: persistent grid-stride version of R3. 1184 CTAs (8/SM) each stream
// ~14 rows back-to-back: removes the 14-wave launch structure and lets row
// n+1's LDGs overlap row n's MUFU chain (cross-row MLP without register blowup).

#define LATTICE 4096
#define THREADS 256
#define GRID_BLOCKS (148 * 8)

__global__ __launch_bounds__(THREADS) void xy_hamiltonian_kernel(
    const float* __restrict__ state,
    float* __restrict__ out,
    int n_samples)
{
    __shared__ float warp_sums[THREADS / 32];

    const int tid  = threadIdx.x;
    const int lane = tid & 31;
    // Right-neighbor source lane: within each 16-lane group (one 64-site
    // lattice row = 16 float4), lane L's boundary right-neighbor is lane
    // L+1's a.x, wrapping to the group's first lane at col 63.
    const int src_lane = (lane & ~15) | ((lane + 1) & 15);

    for (int row = blockIdx.x; row < n_samples; row += gridDim.x) {
        const float4* __restrict__ rp4 =
            reinterpret_cast<const float4*>(state + (size_t)row * LATTICE);

        float acc = 0.0f;
        #pragma unroll
        for (int k = 0; k < 4; k++) {
            const int m = tid + k * THREADS;                  // float4 idx 0..1023
            const float4 a = rp4[m];                          // own sites
            const float4 b = rp4[(m + 16) & (LATTICE/4 - 1)]; // up neighbors (+64, periodic)
            const float xr3 = __shfl_sync(0xffffffffu, a.x, src_lane);

            acc += __cosf(b.x - a.x);   // up bonds
            acc += __cosf(b.y - a.y);
            acc += __cosf(b.z - a.z);
            acc += __cosf(b.w - a.w);
            acc += __cosf(a.y - a.x);   // right bonds
            acc += __cosf(a.z - a.y);
            acc += __cosf(a.w - a.z);
            acc += __cosf(xr3 - a.w);
        }

        // Warp reduce
        #pragma unroll
        for (int o = 16; o > 0; o >>= 1)
            acc += __shfl_down_sync(0xffffffffu, acc, o);
        if (lane == 0)
            warp_sums[tid >> 5] = acc;
        __syncthreads();

        if (tid < 8) {
            float v = warp_sums[tid];
            #pragma unroll
            for (int o = 4; o > 0; o >>= 1)
                v += __shfl_down_sync(0x000000ffu, v, o);
            if (tid == 0)
                out[row] = v;
        }
        __syncthreads();   // warp_sums reuse across iterations
    }
}

extern "C" void kernel_launch(void* const* d_in, const int* in_sizes, int n_in,
                              void* d_out, int out_size)
{
    const float* state = (const float*)d_in[0];
    // d_in[1] (shift table, int64) is reproduced arithmetically in-kernel.
    float* out = (float*)d_out;

    const int n_samples = in_sizes[0] / LATTICE;  // 16384
    const int blocks = (n_samples < GRID_BLOCKS) ? n_samples : GRID_BLOCKS;
    xy_hamiltonian_kernel<<<blocks, THREADS>>>(state, out, n_samples);
}

// round 6
// speedup vs baseline: 1.0454x; 1.0454x over previous
#include <cuda_runtime.h>

// XY model log-density: out[s] = sum_i cos(x[up(i)] - x[i]) + cos(x[right(i)] - x[i])
// 64x64 lattice (4096 sites), 16384 samples, BETA = 1.
//
// R6: R4's front-batched loads + __launch_bounds__(256, 4) so ptxas actually
// grants the registers (R4 failed because the default occupancy heuristic
// capped regs at 32 and re-serialized the loads). 8 LDG.128 in flight per
// thread; 4 CTAs/SM doubles in-flight bytes per SM.

#define LATTICE 4096
#define THREADS 256

__global__ __launch_bounds__(THREADS, 4) void xy_hamiltonian_kernel(
    const float* __restrict__ state,
    float* __restrict__ out)
{
    __shared__ float warp_sums[THREADS / 32];

    const int tid  = threadIdx.x;
    const int lane = tid & 31;
    const float4* __restrict__ rp4 =
        reinterpret_cast<const float4*>(state + (size_t)blockIdx.x * LATTICE);

    const int m0 = tid;
    const int m1 = tid + 256;
    const int m2 = tid + 512;
    const int m3 = tid + 768;

    // ---- front-batched loads: 8 independent LDG.128 in flight ----
    const float4 a0 = rp4[m0];
    const float4 a1 = rp4[m1];
    const float4 a2 = rp4[m2];
    const float4 a3 = rp4[m3];
    const float4 b0 = rp4[(m0 + 16) & (LATTICE/4 - 1)];
    const float4 b1 = rp4[(m1 + 16) & (LATTICE/4 - 1)];
    const float4 b2 = rp4[(m2 + 16) & (LATTICE/4 - 1)];
    const float4 b3 = rp4[(m3 + 16) & (LATTICE/4 - 1)];

    // Right-neighbor source lane: within each 16-lane group (one 64-site
    // lattice row = 16 float4), lane L's boundary right-neighbor is lane
    // L+1's a.x, wrapping to the group's first lane at col 63.
    const int src_lane = (lane & ~15) | ((lane + 1) & 15);
    const float xr0 = __shfl_sync(0xffffffffu, a0.x, src_lane);
    const float xr1 = __shfl_sync(0xffffffffu, a1.x, src_lane);
    const float xr2 = __shfl_sync(0xffffffffu, a2.x, src_lane);
    const float xr3 = __shfl_sync(0xffffffffu, a3.x, src_lane);

    float acc = 0.0f;
    // up bonds
    acc += __cosf(b0.x - a0.x); acc += __cosf(b0.y - a0.y);
    acc += __cosf(b0.z - a0.z); acc += __cosf(b0.w - a0.w);
    acc += __cosf(b1.x - a1.x); acc += __cosf(b1.y - a1.y);
    acc += __cosf(b1.z - a1.z); acc += __cosf(b1.w - a1.w);
    acc += __cosf(b2.x - a2.x); acc += __cosf(b2.y - a2.y);
    acc += __cosf(b2.z - a2.z); acc += __cosf(b2.w - a2.w);
    acc += __cosf(b3.x - a3.x); acc += __cosf(b3.y - a3.y);
    acc += __cosf(b3.z - a3.z); acc += __cosf(b3.w - a3.w);
    // right bonds (intra-float4 + boundary via shuffle)
    acc += __cosf(a0.y - a0.x); acc += __cosf(a0.z - a0.y);
    acc += __cosf(a0.w - a0.z); acc += __cosf(xr0  - a0.w);
    acc += __cosf(a1.y - a1.x); acc += __cosf(a1.z - a1.y);
    acc += __cosf(a1.w - a1.z); acc += __cosf(xr1  - a1.w);
    acc += __cosf(a2.y - a2.x); acc += __cosf(a2.z - a2.y);
    acc += __cosf(a2.w - a2.z); acc += __cosf(xr2  - a2.w);
    acc += __cosf(a3.y - a3.x); acc += __cosf(a3.z - a3.y);
    acc += __cosf(a3.w - a3.z); acc += __cosf(xr3  - a3.w);

    // Warp reduce
    #pragma unroll
    for (int o = 16; o > 0; o >>= 1)
        acc += __shfl_down_sync(0xffffffffu, acc, o);
    if (lane == 0)
        warp_sums[tid >> 5] = acc;
    __syncthreads();

    if (tid < 8) {
        float v = warp_sums[tid];
        #pragma unroll
        for (int o = 4; o > 0; o >>= 1)
            v += __shfl_down_sync(0x000000ffu, v, o);
        if (tid == 0)
            out[blockIdx.x] = v;
    }
}

extern "C" void kernel_launch(void* const* d_in, const int* in_sizes, int n_in,
                              void* d_out, int out_size)
{
    const float* state = (const float*)d_in[0];
    // d_in[1] (shift table, int64) is reproduced arithmetically in-kernel.
    float* out = (float*)d_out;

    const int n_samples = in_sizes[0] / LATTICE;  // 16384
    xy_hamiltonian_kernel<<<n_samples, THREADS>>>(state, out);
}

// round 7
// speedup vs baseline: 1.1000x; 1.0522x over previous
#include <cuda_runtime.h>

// XY model log-density: out[s] = sum_i cos(x[up(i)] - x[i]) + cos(x[right(i)] - x[i])
// 64x64 lattice (4096 sites), 16384 samples, BETA = 1.
//
// R7: R3 (best: 43.7us, DRAM 81%) + evict-first (.cs) loads. The 256MB stream
// is 2x L2 capacity with no long-distance reuse; evict-first cuts L2
// replacement churn for better DRAM efficiency.

#define LATTICE 4096
#define THREADS 256

__global__ __launch_bounds__(THREADS) void xy_hamiltonian_kernel(
    const float* __restrict__ state,
    float* __restrict__ out)
{
    __shared__ float warp_sums[THREADS / 32];

    const int tid  = threadIdx.x;
    const int lane = tid & 31;
    const float4* __restrict__ rp4 =
        reinterpret_cast<const float4*>(state + (size_t)blockIdx.x * LATTICE);

    // Right-neighbor source lane: within each 16-lane group (one 64-site
    // lattice row = 16 float4), lane L's boundary right-neighbor is lane
    // L+1's a.x, wrapping to the group's first lane at col 63.
    const int src_lane = (lane & ~15) | ((lane + 1) & 15);

    float acc = 0.0f;
    #pragma unroll
    for (int k = 0; k < 4; k++) {
        const int m = tid + k * THREADS;                        // float4 idx 0..1023
        const float4 a = __ldcs(&rp4[m]);                       // own sites (evict-first)
        const float4 b = __ldcs(&rp4[(m + 16) & (LATTICE/4 - 1)]); // up neighbors (+64, periodic)
        const float xr3 = __shfl_sync(0xffffffffu, a.x, src_lane);

        acc += __cosf(b.x - a.x);   // up bonds
        acc += __cosf(b.y - a.y);
        acc += __cosf(b.z - a.z);
        acc += __cosf(b.w - a.w);
        acc += __cosf(a.y - a.x);   // right bonds
        acc += __cosf(a.z - a.y);
        acc += __cosf(a.w - a.z);
        acc += __cosf(xr3 - a.w);
    }

    // Warp reduce
    #pragma unroll
    for (int o = 16; o > 0; o >>= 1)
        acc += __shfl_down_sync(0xffffffffu, acc, o);
    if (lane == 0)
        warp_sums[tid >> 5] = acc;
    __syncthreads();

    if (tid < 8) {
        float v = warp_sums[tid];
        #pragma unroll
        for (int o = 4; o > 0; o >>= 1)
            v += __shfl_down_sync(0x000000ffu, v, o);
        if (tid == 0)
            out[blockIdx.x] = v;
    }
}

extern "C" void kernel_launch(void* const* d_in, const int* in_sizes, int n_in,
                              void* d_out, int out_size)
{
    const float* state = (const float*)d_in[0];
    // d_in[1] (shift table, int64) is reproduced arithmetically in-kernel.
    float* out = (float*)d_out;

    const int n_samples = in_sizes[0] / LATTICE;  // 16384
    xy_hamiltonian_kernel<<<n_samples, THREADS>>>(state, out);
}